// round 3
// baseline (speedup 1.0000x reference)
#include <cuda_runtime.h>
#include <cstdint>

#define NQ   14
#define TPB  512
typedef unsigned long long ull;

// Storage swizzle: conflict-free for every access pattern used below.
__device__ __forceinline__ int phys_(int j) { return j ^ ((j >> 4) & 15); }

// Forward CNOT-chain index map: bit k of result = parity of bits k..13 of x.
__device__ __forceinline__ int pf_(int x) {
    x ^= x >> 1; x ^= x >> 2; x ^= x >> 4; x ^= x >> 8;
    return x;
}

// ---- packed f32x2 on native 64-bit registers (no pack/unpack movs) ----
__device__ __forceinline__ ull f2mul(ull a, ull b) {
    ull r; asm("mul.rn.f32x2 %0,%1,%2;" : "=l"(r) : "l"(a), "l"(b)); return r;
}
__device__ __forceinline__ ull f2fma(ull a, ull b, ull c) {
    ull r; asm("fma.rn.f32x2 %0,%1,%2,%3;" : "=l"(r) : "l"(a), "l"(b), "l"(c)); return r;
}
__device__ __forceinline__ ull pk2(float x, float y) {
    ull r; asm("mov.b64 %0,{%1,%2};" : "=l"(r) : "f"(x), "f"(y)); return r;
}
__device__ __forceinline__ float2 upk(ull a) {
    float2 r; asm("mov.b64 {%0,%1},%2;" : "=f"(r.x), "=f"(r.y) : "l"(a)); return r;
}
__device__ __forceinline__ ull swp(ull a) { float2 t = upk(a); return pk2(t.y, t.x); }
__device__ __forceinline__ ull bcast(float x) { return pk2(x, x); }

// RY rotation on a pair (re/im packed in each ull).
__device__ __forceinline__ void ry_pair(ull& u0, ull& u1, ull ca2, ull sa2, ull nsa2) {
    ull t0 = f2fma(nsa2, u1, f2mul(ca2, u0));
    ull t1 = f2fma(ca2,  u1, f2mul(sa2, u0));
    u0 = t0; u1 = t1;
}

// a * phase, phase pre-split: px=(pr,pr), pm=(-pi,pi).
__device__ __forceinline__ ull cmulp(ull a, ull px, ull pm) {
    return f2fma(px, a, f2mul(pm, swp(a)));
}

// scalar complex mul (LUT build only)
__device__ __forceinline__ float2 cmul_s(float2 a, float2 b) {
    return make_float2(a.x * b.x - a.y * b.y, a.x * b.y + a.y * b.x);
}

__global__ void __launch_bounds__(TPB, 1)
qsim_kernel(const float* __restrict__ sb,   // [B,14]
            const float* __restrict__ vp,   // [3,14,3]
            const float* __restrict__ hw,   // [1,14]
            const float* __restrict__ hb,   // [1]
            float* __restrict__ out)        // [B]
{
    extern __shared__ unsigned char smraw[];
    ull*    psi  = (ull*)smraw;                         // 131072 B (16384 ull)
    ull*    PloX = psi + 16384;                         // 3*128
    ull*    PloM = PloX + 384;                          // 3*128
    ull*    PhiX = PloM + 384;                          // 3*128
    ull*    PhiM = PhiX + 384;                          // 3*128
    float2* gRY  = (float2*)(PhiM + 384);               // 48 (42 used)
    float2* phw  = gRY + 48;                            // 48 (42 used)
    float*  cx   = (float*)(phw + 48);                  // 16
    float*  sx   = cx + 16;                             // 16
    float*  Wlo  = sx + 16;                             // 128
    float*  Whi  = Wlo + 128;                           // 128
    float*  red  = Whi + 128;                           // 16

    const int t = threadIdx.x;
    const int b = blockIdx.x;

    // ---- stage 1: tiny parameter staging ----
    if (t < NQ) {
        float s, c;
        sincosf(0.5f * sb[b * NQ + t], &s, &c);
        cx[t] = c; sx[t] = s;
    }
    if (t >= 64 && t < 64 + 3 * NQ) {
        int lw = t - 64;                         // L*14 + w
        float sa, ca, sp, cp;
        sincosf(0.5f * vp[lw * 3 + 0], &sa, &ca);
        sincosf(vp[lw * 3 + 1], &sp, &cp);       // RZ -> diag(1, e^{i theta})
        gRY[lw] = make_float2(ca, sa);
        phw[lw] = make_float2(cp, sp);
    }
    if (t >= 128 && t < 256) {                   // W for bits 0..6 (wires 13..7)
        int v = t - 128; float acc = 0.f;
        #pragma unroll
        for (int k = 0; k < 7; k++)
            acc += hw[13 - k] * (1.f - 2.f * (float)((v >> k) & 1));
        Wlo[v] = acc;
    }
    if (t >= 256 && t < 384) {                   // W for bits 7..13 (wires 6..0)
        int v = t - 256; float acc = 0.f;
        #pragma unroll
        for (int k = 0; k < 7; k++)
            acc += hw[6 - k] * (1.f - 2.f * (float)((v >> k) & 1));
        Whi[v] = acc;
    }
    __syncthreads();

    // ---- stage 2: per-layer consolidated RZ phase LUTs, pre-split packed ----
    if (t < 384) {
        int L = t >> 7, vv = t & 127;
        float2 pl = make_float2(1.f, 0.f), ph = make_float2(1.f, 0.f);
        #pragma unroll
        for (int k = 0; k < 7; k++) {
            if ((vv >> k) & 1) {
                pl = cmul_s(pl, phw[L * NQ + (13 - k)]);
                ph = cmul_s(ph, phw[L * NQ + (6 - k)]);
            }
        }
        PloX[t] = pk2(pl.x, pl.x);  PloM[t] = pk2(-pl.y, pl.y);
        PhiX[t] = pk2(ph.x, ph.x);  PhiM[t] = pk2(-ph.y, ph.y);
    }

    ull v[32];

    // ---- group-gate appliers (RY only; indices compile-time after unroll) ----
    auto applyA = [&](int L) {                   // wires 0..4 on bits 13..9
        #pragma unroll
        for (int lb = 0; lb < 5; lb++) {
            float2 g = gRY[L * NQ + (4 - lb)];
            ull ca2 = bcast(g.x), sa2 = bcast(g.y), nsa2 = bcast(-g.y);
            #pragma unroll
            for (int m = 0; m < 16; m++) {
                int l0 = ((m >> lb) << (lb + 1)) | (m & ((1 << lb) - 1));
                ry_pair(v[l0], v[l0 | (1 << lb)], ca2, sa2, nsa2);
            }
        }
    };
    auto applyB = [&](int L) {                   // wires 5..9 on bits 8..4
        #pragma unroll
        for (int lb = 0; lb < 5; lb++) {
            float2 g = gRY[L * NQ + (9 - lb)];
            ull ca2 = bcast(g.x), sa2 = bcast(g.y), nsa2 = bcast(-g.y);
            #pragma unroll
            for (int m = 0; m < 16; m++) {
                int l0 = ((m >> lb) << (lb + 1)) | (m & ((1 << lb) - 1));
                ry_pair(v[l0], v[l0 | (1 << lb)], ca2, sa2, nsa2);
            }
        }
    };
    auto applyC16 = [&](int L) {                 // wires 10..13 on bits 3..0
        #pragma unroll
        for (int lb = 0; lb < 4; lb++) {
            float2 g = gRY[L * NQ + (13 - lb)];
            ull ca2 = bcast(g.x), sa2 = bcast(g.y), nsa2 = bcast(-g.y);
            #pragma unroll
            for (int m = 0; m < 8; m++) {
                int l0 = ((m >> lb) << (lb + 1)) | (m & ((1 << lb) - 1));
                ry_pair(v[l0], v[l0 | (1 << lb)], ca2, sa2, nsa2);
            }
        }
    };

    // ---- pass 0: closed-form RX product state + layer0 wires 0..4 ----
    {
        float mt = 1.f;
        #pragma unroll
        for (int k = 0; k < 9; k++)
            mt *= ((t >> k) & 1) ? sx[13 - k] : cx[13 - k];
        int pt = __popc(t);
        #pragma unroll
        for (int l = 0; l < 32; l++) {
            float m = mt;
            #pragma unroll
            for (int lb = 0; lb < 5; lb++)
                m *= ((l >> lb) & 1) ? sx[4 - lb] : cx[4 - lb];
            int k = (pt + __popc(l)) & 3;        // (-i)^k
            float re = (k == 0) ? m : ((k == 2) ? -m : 0.f);
            float im = (k == 1) ? -m : ((k == 3) ? m : 0.f);
            v[l] = pk2(re, im);
        }
        applyA(0);
        #pragma unroll
        for (int l = 0; l < 32; l++)
            psi[phys_((l << 9) | t)] = v[l];
    }
    __syncthreads();

    #pragma unroll 1
    for (int L = 0; L < 3; L++) {
        // ---- pass B: wires 5..9 ----
        {
            const int hi = (t >> 4) << 9;
            const int lo = t & 15;
            #pragma unroll
            for (int l = 0; l < 32; l++)
                v[l] = psi[phys_(hi | (l << 4) | lo)];
            applyB(L);
            #pragma unroll
            for (int l = 0; l < 32; l++)
                psi[phys_(hi | (l << 4) | lo)] = v[l];
        }
        __syncthreads();

        // ---- pass C: wires 10..13 + consolidated layer phase ----
        #pragma unroll
        for (int h = 0; h < 2; h++) {
            const int tt = t + h * TPB;
            #pragma unroll
            for (int l = 0; l < 16; l++)
                v[l] = psi[phys_((tt << 4) | l)];
            applyC16(L);
            {
                ull phx = PhiX[L * 128 + (tt >> 3)];
                ull phm = PhiM[L * 128 + (tt >> 3)];
                const int lobase = L * 128 + ((tt & 7) << 4);
                #pragma unroll
                for (int l = 0; l < 16; l++) {
                    ull a = cmulp(v[l], PloX[lobase | l], PloM[lobase | l]);
                    v[l] = cmulp(a, phx, phm);
                }
            }
            #pragma unroll
            for (int l = 0; l < 16; l++)
                psi[phys_((tt << 4) | l)] = v[l];
        }
        __syncthreads();

        if (L < 2) {
            // ---- pass A' of next layer: CNOT-chain fold (read at F^{-1}(j)) ----
            #pragma unroll
            for (int l = 0; l < 32; l++) {
                int j = (l << 9) | t;
                v[l] = psi[phys_(j ^ (j >> 1))];
            }
            applyA(L + 1);
            __syncthreads();
            #pragma unroll
            for (int l = 0; l < 32; l++)
                psi[phys_((l << 9) | t)] = v[l];
            __syncthreads();
        }
    }

    // ---- measurement: final chain folded into weight lookup ----
    float acc = 0.f;
    #pragma unroll
    for (int k = 0; k < 32; k++) {
        int i = t + (k << 9);
        float2 a = upk(psi[phys_(i)]);
        int f = pf_(i);
        acc += (a.x * a.x + a.y * a.y) * (Wlo[f & 127] + Whi[f >> 7]);
    }
    #pragma unroll
    for (int o = 16; o > 0; o >>= 1)
        acc += __shfl_xor_sync(0xffffffffu, acc, o);
    if ((t & 31) == 0) red[t >> 5] = acc;
    __syncthreads();
    if (t == 0) {
        float s = 0.f;
        #pragma unroll
        for (int w = 0; w < TPB / 32; w++) s += red[w];
        out[b] = s + hb[0];
    }
}

extern "C" void kernel_launch(void* const* d_in, const int* in_sizes, int n_in,
                              void* d_out, int out_size) {
    const float* sb = (const float*)d_in[0];
    const float* vp = (const float*)d_in[1];
    const float* hw = (const float*)d_in[2];
    const float* hb = (const float*)d_in[3];
    float* out = (float*)d_out;

    const int B = in_sizes[0] / NQ;
    const size_t smem = 131072                 // psi
                      + 4 * 384 * 8            // PloX/PloM/PhiX/PhiM
                      + 48 * 8 + 48 * 8        // gRY, phw
                      + 64 + 64                // cx, sx
                      + 512 + 512              // Wlo, Whi
                      + 64;                    // red
    cudaFuncSetAttribute(qsim_kernel,
                         cudaFuncAttributeMaxDynamicSharedMemorySize, (int)smem);
    qsim_kernel<<<B, TPB, smem>>>(sb, vp, hw, hb, out);
}

// round 4
// speedup vs baseline: 1.2833x; 1.2833x over previous
#include <cuda_runtime.h>
#include <cstdint>

#define NQ   14
#define TPB  512
typedef unsigned long long ull;

// pair-address swizzle: conflict-free for all pass patterns below
__device__ __forceinline__ int P_(int p) { return p ^ ((p >> 4) & 15); }

// forward CNOT-chain map: bit k of result = parity of bits k..13
__device__ __forceinline__ int pf_(int x) {
    x ^= x >> 1; x ^= x >> 2; x ^= x >> 4; x ^= x >> 8;
    return x;
}

// ---- packed f32x2 on native 64-bit regs ----
__device__ __forceinline__ ull f2mul(ull a, ull b) {
    ull r; asm("mul.rn.f32x2 %0,%1,%2;" : "=l"(r) : "l"(a), "l"(b)); return r;
}
__device__ __forceinline__ ull f2fma(ull a, ull b, ull c) {
    ull r; asm("fma.rn.f32x2 %0,%1,%2,%3;" : "=l"(r) : "l"(a), "l"(b), "l"(c)); return r;
}
__device__ __forceinline__ ull pk2(float x, float y) {
    ull r; asm("mov.b64 %0,{%1,%2};" : "=l"(r) : "f"(x), "f"(y)); return r;
}
__device__ __forceinline__ float2 upk(ull a) {
    float2 r; asm("mov.b64 {%0,%1},%2;" : "=f"(r.x), "=f"(r.y) : "l"(a)); return r;
}
__device__ __forceinline__ ull swp(ull a) { float2 t = upk(a); return pk2(t.y, t.x); }
__device__ __forceinline__ ull bc(float x) { return pk2(x, x); }

// RY on register pair (each reg packs 2 amplitudes along a non-gate bit)
__device__ __forceinline__ void ryp(ull& u0, ull& u1, ull ca, ull sa, ull nsa) {
    ull t0 = f2fma(nsa, u1, f2mul(ca, u0));
    ull t1 = f2fma(ca,  u1, f2mul(sa, u0));
    u0 = t0; u1 = t1;
}

__device__ __forceinline__ float2 cmul_s(float2 a, float2 b) {
    return make_float2(a.x * b.x - a.y * b.y, a.x * b.y + a.y * b.x);
}

__global__ void __launch_bounds__(TPB, 1)
qsim_kernel(const float* __restrict__ sb, const float* __restrict__ vp,
            const float* __restrict__ hw, const float* __restrict__ hb,
            float* __restrict__ out)
{
    extern __shared__ unsigned char smraw[];
    ull*    sRe   = (ull*)smraw;            // 8192
    ull*    sIm   = sRe + 8192;             // 8192
    ull*    PloRe = sIm + 8192;             // 3*64, layout [L][r*4+c]
    ull*    PloIm = PloRe + 192;            // 3*64
    ull*    Wlo2  = PloIm + 192;            // 64 (scalar view: Wlo[128])
    float2* gRY   = (float2*)(Wlo2 + 64);   // 48 (42 used)
    float2* phw   = gRY + 48;               // 48
    float*  PhiRe = (float*)(phw + 48);     // 384
    float*  PhiIm = PhiRe + 384;            // 384
    float*  cx    = PhiIm + 384;            // 16
    float*  sx    = cx + 16;                // 16
    float*  Whi   = sx + 16;                // 128
    float*  red   = Whi + 128;              // 16
    float*  WloF  = (float*)Wlo2;

    const int t = threadIdx.x;
    const int b = blockIdx.x;

    // ---- stage 1 ----
    if (t < NQ) {
        float s, c; sincosf(0.5f * sb[b * NQ + t], &s, &c);
        cx[t] = c; sx[t] = s;
    }
    if (t >= 64 && t < 64 + 3 * NQ) {
        int lw = t - 64;
        float sa, ca, sp, cp;
        sincosf(0.5f * vp[lw * 3 + 0], &sa, &ca);
        sincosf(vp[lw * 3 + 1], &sp, &cp);
        gRY[lw] = make_float2(ca, sa);
        phw[lw] = make_float2(cp, sp);
    }
    if (t >= 128 && t < 256) {                   // Wlo(v), v = f bits 0..6
        int v = t - 128; float acc = 0.f;
        #pragma unroll
        for (int k = 0; k < 7; k++)
            acc += hw[13 - k] * (1.f - 2.f * (float)((v >> k) & 1));
        WloF[v] = acc;
    }
    if (t >= 256 && t < 384) {                   // Whi(v), v = f bits 7..13
        int v = t - 256; float acc = 0.f;
        #pragma unroll
        for (int k = 0; k < 7; k++)
            acc += hw[6 - k] * (1.f - 2.f * (float)((v >> k) & 1));
        Whi[v] = acc;
    }
    __syncthreads();

    // ---- stage 2: consolidated per-layer RZ phase LUTs ----
    if (t < 384) {
        int L = t >> 7, v = t & 127;
        float2 pl = make_float2(1.f, 0.f), ph = make_float2(1.f, 0.f);
        #pragma unroll
        for (int k = 0; k < 7; k++) {
            if ((v >> k) & 1) {
                pl = cmul_s(pl, phw[L * NQ + (13 - k)]);   // i bits 0..6
                ph = cmul_s(ph, phw[L * NQ + (6 - k)]);    // i bits 7..13
            }
        }
        PhiRe[t] = ph.x; PhiIm[t] = ph.y;
        int c = v >> 5, r = (v >> 1) & 15, b0 = v & 1;     // transposed, packed bit0
        ((float*)PloRe)[2 * (L * 64 + r * 4 + c) + b0] = pl.x;
        ((float*)PloIm)[2 * (L * 64 + r * 4 + c) + b0] = pl.y;
    }

    ull vre[16], vim[16];

    // gates on local reg bit lb (pairs across registers), lane-symmetric
    auto applyW = [&](float2 g, int lb) {
        ull ca = bc(g.x), sa = bc(g.y), nsa = bc(-g.y);
        #pragma unroll
        for (int m = 0; m < 8; m++) {
            int l0 = ((m >> lb) << (lb + 1)) | (m & ((1 << lb) - 1));
            int l1 = l0 | (1 << lb);
            ryp(vre[l0], vre[l1], ca, sa, nsa);
            ryp(vim[l0], vim[l1], ca, sa, nsa);
        }
    };

    // ---- init: closed-form RX + P1(layer 0) gates (wires 0..3) ----
    {
        float mt = 1.f;
        #pragma unroll
        for (int k = 0; k < 9; k++)               // t = i bits 9..1, wire 12-k
            mt *= ((t >> k) & 1) ? sx[12 - k] : cx[12 - k];
        int pt = __popc(t);
        #pragma unroll
        for (int r = 0; r < 16; r++) {            // r = i bits 13..10
            float mr = mt;
            #pragma unroll
            for (int m = 0; m < 4; m++)
                mr *= ((r >> m) & 1) ? sx[3 - m] : cx[3 - m];
            int pr = pt + __popc(r);
            float m0 = mr * cx[13], m1 = mr * sx[13];
            int k0 = pr & 3, k1 = (pr + 1) & 3;
            float re0 = (k0 == 0) ? m0 : ((k0 == 2) ? -m0 : 0.f);
            float im0 = (k0 == 1) ? -m0 : ((k0 == 3) ? m0 : 0.f);
            float re1 = (k1 == 0) ? m1 : ((k1 == 2) ? -m1 : 0.f);
            float im1 = (k1 == 1) ? -m1 : ((k1 == 3) ? m1 : 0.f);
            vre[r] = pk2(re0, re1); vim[r] = pk2(im0, im1);
        }
        #pragma unroll
        for (int lb = 0; lb < 4; lb++) applyW(gRY[3 - lb], lb);
        #pragma unroll
        for (int r = 0; r < 16; r++) {
            int p = P_((r << 9) | t);
            sRe[p] = vre[r]; sIm[p] = vim[r];
        }
    }
    __syncthreads();

    #pragma unroll 1
    for (int L = 0; L < 3; L++) {
        // ---- P2: i bits 9..6 (wires 4..7) ----
        {
            const int base = ((t >> 5) << 9) | (t & 31);
            #pragma unroll
            for (int r = 0; r < 16; r++) {
                int p = P_(base | (r << 5));
                vre[r] = sRe[p]; vim[r] = sIm[p];
            }
            #pragma unroll
            for (int lb = 0; lb < 4; lb++) applyW(gRY[L * NQ + (7 - lb)], lb);
            #pragma unroll
            for (int r = 0; r < 16; r++) {
                int p = P_(base | (r << 5));
                sRe[p] = vre[r]; sIm[p] = vim[r];
            }
        }
        __syncthreads();

        // ---- P3: i bits 5..2 (wires 8..11) ----
        {
            const int base = ((t >> 1) << 5) | (t & 1);
            #pragma unroll
            for (int r = 0; r < 16; r++) {
                int p = P_(base | (r << 1));
                vre[r] = sRe[p]; vim[r] = sIm[p];
            }
            #pragma unroll
            for (int lb = 0; lb < 4; lb++) applyW(gRY[L * NQ + (11 - lb)], lb);
            #pragma unroll
            for (int r = 0; r < 16; r++) {
                int p = P_(base | (r << 1));
                sRe[p] = vre[r]; sIm[p] = vim[r];
            }
        }
        __syncthreads();

        // ---- P4: i bits 1,0 (wires 12,13) + consolidated layer phase ----
        {
            #pragma unroll
            for (int r = 0; r < 16; r++) {
                int p = P_((t << 4) | r);
                vre[r] = sRe[p]; vim[r] = sIm[p];
            }
            applyW(gRY[L * NQ + 12], 0);             // wire 12: cross-register
            {                                         // wire 13: in-register lanes
                float2 g = gRY[L * NQ + 13];
                ull ca = bc(g.x), nsps = pk2(-g.y, g.y);
                #pragma unroll
                for (int r = 0; r < 16; r++) {
                    vre[r] = f2fma(ca, vre[r], f2mul(nsps, swp(vre[r])));
                    vim[r] = f2fma(ca, vim[r], f2mul(nsps, swp(vim[r])));
                }
            }
            {                                         // layer phase
                float fr = PhiRe[L * 128 + (t >> 2)];
                float fi = PhiIm[L * 128 + (t >> 2)];
                ull fr2 = bc(fr), fi2 = bc(fi), nfi2 = bc(-fi), n1 = bc(-1.f);
                const int c = t & 3;
                #pragma unroll
                for (int r = 0; r < 16; r++) {
                    ull pr2 = PloRe[L * 64 + r * 4 + c];
                    ull pi2 = PloIm[L * 64 + r * 4 + c];
                    ull cr  = f2fma(fr2, pr2, f2mul(nfi2, pi2));
                    ull ci  = f2fma(fr2, pi2, f2mul(fi2, pr2));
                    ull nci = f2mul(n1, ci);
                    ull re = vre[r], im = vim[r];
                    vre[r] = f2fma(cr, re, f2mul(nci, im));
                    vim[r] = f2fma(cr, im, f2mul(ci,  re));
                }
            }
            #pragma unroll
            for (int r = 0; r < 16; r++) {
                int p = P_((t << 4) | r);
                sRe[p] = vre[r]; sIm[p] = vim[r];
            }
        }
        __syncthreads();

        if (L < 2) {
            // ---- P1 of next layer with CNOT-chain fold ----
            // output pair q=(r<<9)|t reads input pair pm = q ^ (q>>1);
            // lanes swapped iff (q&1) == (t&1) == 1 (uniform per thread).
            #pragma unroll
            for (int r = 0; r < 16; r++) {
                int q = (r << 9) | t;
                int p = P_(q ^ (q >> 1));
                vre[r] = sRe[p]; vim[r] = sIm[p];
            }
            if (t & 1) {
                #pragma unroll
                for (int r = 0; r < 16; r++) { vre[r] = swp(vre[r]); vim[r] = swp(vim[r]); }
            }
            __syncthreads();   // all reads done before any rewrite
            #pragma unroll
            for (int lb = 0; lb < 4; lb++) applyW(gRY[(L + 1) * NQ + (3 - lb)], lb);
            #pragma unroll
            for (int r = 0; r < 16; r++) {
                int p = P_((r << 9) | t);
                sRe[p] = vre[r]; sIm[p] = vim[r];
            }
            __syncthreads();
        }
    }

    // ---- measurement: final chain folded into weight lookup (packed) ----
    {
        const int ftt = pf_(t << 5);
        ull acc2 = bc(0.f);
        #pragma unroll
        for (int k = 0; k < 16; k++) {
            int p = P_((t << 4) | k);
            ull re = sRe[p], im = sIm[p];
            ull pr2 = f2fma(im, im, f2mul(re, re));      // (|a0|^2, |a1|^2)
            int f0 = ftt ^ pf_(k << 1);                  // pf_(k<<1) folds at compile time
            float w0 = WloF[f0 & 127]       + Whi[f0 >> 7];
            float w1 = WloF[(f0 ^ 1) & 127] + Whi[f0 >> 7];
            acc2 = f2fma(pr2, pk2(w0, w1), acc2);
        }
        float2 ac = upk(acc2);
        float acc = ac.x + ac.y;
        #pragma unroll
        for (int o = 16; o > 0; o >>= 1)
            acc += __shfl_xor_sync(0xffffffffu, acc, o);
        if ((t & 31) == 0) red[t >> 5] = acc;
        __syncthreads();
        if (t == 0) {
            float s = 0.f;
            #pragma unroll
            for (int w = 0; w < TPB / 32; w++) s += red[w];
            out[b] = s + hb[0];
        }
    }
}

extern "C" void kernel_launch(void* const* d_in, const int* in_sizes, int n_in,
                              void* d_out, int out_size) {
    const float* sb = (const float*)d_in[0];
    const float* vp = (const float*)d_in[1];
    const float* hw = (const float*)d_in[2];
    const float* hb = (const float*)d_in[3];
    float* out = (float*)d_out;

    const int B = in_sizes[0] / NQ;
    const size_t smem = (8192 * 2 + 192 * 2 + 64) * 8   // sRe,sIm,PloRe,PloIm,Wlo2
                      + 96 * 8                          // gRY, phw
                      + (384 * 2 + 32 + 128 + 16) * 4;  // PhiRe/Im, cx,sx, Whi, red
    cudaFuncSetAttribute(qsim_kernel,
                         cudaFuncAttributeMaxDynamicSharedMemorySize, (int)smem);
    qsim_kernel<<<B, TPB, smem>>>(sb, vp, hw, hb, out);
}

// round 5
// speedup vs baseline: 1.4261x; 1.1113x over previous
#include <cuda_runtime.h>
#include <cstdint>

#define NQ   14
#define TPB  512
typedef unsigned long long ull;

// forward CNOT-chain map: bit k of result = parity of bits k..13
__device__ __forceinline__ int pf_(int x) {
    x ^= x >> 1; x ^= x >> 2; x ^= x >> 4; x ^= x >> 8;
    return x;
}

// ---- packed f32x2 on native 64-bit regs ----
__device__ __forceinline__ ull f2mul(ull a, ull b) {
    ull r; asm("mul.rn.f32x2 %0,%1,%2;" : "=l"(r) : "l"(a), "l"(b)); return r;
}
__device__ __forceinline__ ull f2fma(ull a, ull b, ull c) {
    ull r; asm("fma.rn.f32x2 %0,%1,%2,%3;" : "=l"(r) : "l"(a), "l"(b), "l"(c)); return r;
}
__device__ __forceinline__ ull pk2(float x, float y) {
    ull r; asm("mov.b64 %0,{%1,%2};" : "=l"(r) : "f"(x), "f"(y)); return r;
}
__device__ __forceinline__ float2 upk(ull a) {
    float2 r; asm("mov.b64 {%0,%1},%2;" : "=f"(r.x), "=f"(r.y) : "l"(a)); return r;
}
__device__ __forceinline__ ull swp(ull a) { float2 t = upk(a); return pk2(t.y, t.x); }
__device__ __forceinline__ ull bc(float x) { return pk2(x, x); }

__device__ __forceinline__ void ryp(ull& u0, ull& u1, ull ca, ull sa, ull nsa) {
    ull t0 = f2fma(nsa, u1, f2mul(ca, u0));
    ull t1 = f2fma(ca,  u1, f2mul(sa, u0));
    u0 = t0; u1 = t1;
}

__device__ __forceinline__ float2 cmul_s(float2 a, float2 b) {
    return make_float2(a.x * b.x - a.y * b.y, a.x * b.y + a.y * b.x);
}

#define SPAD 8704   // 8192 pairs + 512 pad (1 per 16)

__global__ void __launch_bounds__(TPB, 1)
qsim_kernel(const float* __restrict__ sb, const float* __restrict__ vp,
            const float* __restrict__ hw, const float* __restrict__ hb,
            float* __restrict__ out)
{
    extern __shared__ unsigned char smraw[];
    ull*    sRe   = (ull*)smraw;             // 8704
    ull*    sIm   = sRe + SPAD;              // 8704
    ull*    PloRe = sIm + SPAD;              // 3*64, layout [L][r*4+c]
    ull*    PloIm = PloRe + 192;             // 3*64
    ull*    Wlo2  = PloIm + 192;             // 64 (scalar view Wlo[128])
    float2* gRY   = (float2*)(Wlo2 + 64);    // 48 (42 used)
    float2* phw   = gRY + 48;                // 48
    float*  PhiRe = (float*)(phw + 48);      // 384
    float*  PhiIm = PhiRe + 384;             // 384
    float*  cx    = PhiIm + 384;             // 16
    float*  sx    = cx + 16;                 // 16
    float*  Whi   = sx + 16;                 // 128
    float*  red   = Whi + 128;               // 16
    float*  WloF  = (float*)Wlo2;

    const int t = threadIdx.x;
    const int b = blockIdx.x;

    // ---- stage 1 ----
    if (t < NQ) {
        float s, c; sincosf(0.5f * sb[b * NQ + t], &s, &c);
        cx[t] = c; sx[t] = s;
    }
    if (t >= 64 && t < 64 + 3 * NQ) {
        int lw = t - 64;
        float sa, ca, sp, cp;
        sincosf(0.5f * vp[lw * 3 + 0], &sa, &ca);
        sincosf(vp[lw * 3 + 1], &sp, &cp);
        gRY[lw] = make_float2(ca, sa);
        phw[lw] = make_float2(cp, sp);
    }
    if (t >= 128 && t < 256) {
        int v = t - 128; float acc = 0.f;
        #pragma unroll
        for (int k = 0; k < 7; k++)
            acc += hw[13 - k] * (1.f - 2.f * (float)((v >> k) & 1));
        WloF[v] = acc;
    }
    if (t >= 256 && t < 384) {
        int v = t - 256; float acc = 0.f;
        #pragma unroll
        for (int k = 0; k < 7; k++)
            acc += hw[6 - k] * (1.f - 2.f * (float)((v >> k) & 1));
        Whi[v] = acc;
    }
    __syncthreads();

    // ---- stage 2: consolidated per-layer RZ phase LUTs ----
    if (t < 384) {
        int L = t >> 7, v = t & 127;
        float2 pl = make_float2(1.f, 0.f), ph = make_float2(1.f, 0.f);
        #pragma unroll
        for (int k = 0; k < 7; k++) {
            if ((v >> k) & 1) {
                pl = cmul_s(pl, phw[L * NQ + (13 - k)]);
                ph = cmul_s(ph, phw[L * NQ + (6 - k)]);
            }
        }
        PhiRe[t] = ph.x; PhiIm[t] = ph.y;
        int c = v >> 5, r = (v >> 1) & 15, b0 = v & 1;
        ((float*)PloRe)[2 * (L * 64 + r * 4 + c) + b0] = pl.x;
        ((float*)PloIm)[2 * (L * 64 + r * 4 + c) + b0] = pl.y;
    }

    ull vre[16], vim[16];

    auto applyW = [&](float2 g, int lb) {
        ull ca = bc(g.x), sa = bc(g.y), nsa = bc(-g.y);
        #pragma unroll
        for (int m = 0; m < 8; m++) {
            int l0 = ((m >> lb) << (lb + 1)) | (m & ((1 << lb) - 1));
            int l1 = l0 | (1 << lb);
            ryp(vre[l0], vre[l1], ca, sa, nsa);
            ryp(vim[l0], vim[l1], ca, sa, nsa);
        }
    };

    // affine pass bases (padding A(p) = p + (p>>4))
    const int b1 = t + (t >> 4);                               // + 544*r
    const int b2 = (t >> 5) * 544 + (t & 31) + ((t >> 4) & 1); // + 34*r
    const int b3 = 34 * (t >> 1) + (t & 1);                    // + 2r + (r>>3)
    const int b4 = 17 * t;                                     // + r

    // ---- init: closed-form RX + layer-0 wires 0..3 ----
    {
        float mt = 1.f;
        #pragma unroll
        for (int k = 0; k < 9; k++)
            mt *= ((t >> k) & 1) ? sx[12 - k] : cx[12 - k];
        int pt = __popc(t);
        #pragma unroll
        for (int r = 0; r < 16; r++) {
            float mr = mt;
            #pragma unroll
            for (int m = 0; m < 4; m++)
                mr *= ((r >> m) & 1) ? sx[3 - m] : cx[3 - m];
            int pr = pt + __popc(r);
            float m0 = mr * cx[13], m1 = mr * sx[13];
            int k0 = pr & 3, k1 = (pr + 1) & 3;
            float re0 = (k0 == 0) ? m0 : ((k0 == 2) ? -m0 : 0.f);
            float im0 = (k0 == 1) ? -m0 : ((k0 == 3) ? m0 : 0.f);
            float re1 = (k1 == 0) ? m1 : ((k1 == 2) ? -m1 : 0.f);
            float im1 = (k1 == 1) ? -m1 : ((k1 == 3) ? m1 : 0.f);
            vre[r] = pk2(re0, re1); vim[r] = pk2(im0, im1);
        }
        #pragma unroll
        for (int lb = 0; lb < 4; lb++) applyW(gRY[3 - lb], lb);
        #pragma unroll
        for (int r = 0; r < 16; r++) { sRe[b1 + 544 * r] = vre[r]; sIm[b1 + 544 * r] = vim[r]; }
    }
    __syncthreads();

    #pragma unroll 1
    for (int L = 0; L < 3; L++) {
        // ---- P2: wires 4..7 ----
        {
            #pragma unroll
            for (int r = 0; r < 16; r++) { vre[r] = sRe[b2 + 34 * r]; vim[r] = sIm[b2 + 34 * r]; }
            #pragma unroll
            for (int lb = 0; lb < 4; lb++) applyW(gRY[L * NQ + (7 - lb)], lb);
            #pragma unroll
            for (int r = 0; r < 16; r++) { sRe[b2 + 34 * r] = vre[r]; sIm[b2 + 34 * r] = vim[r]; }
        }
        __syncthreads();

        // ---- P3: wires 8..11 ----
        {
            #pragma unroll
            for (int r = 0; r < 16; r++) {
                int o = b3 + 2 * r + (r >> 3);
                vre[r] = sRe[o]; vim[r] = sIm[o];
            }
            #pragma unroll
            for (int lb = 0; lb < 4; lb++) applyW(gRY[L * NQ + (11 - lb)], lb);
            #pragma unroll
            for (int r = 0; r < 16; r++) {
                int o = b3 + 2 * r + (r >> 3);
                sRe[o] = vre[r]; sIm[o] = vim[r];
            }
        }
        __syncthreads();

        // ---- P4: wires 12,13 + consolidated layer phase ----
        {
            #pragma unroll
            for (int r = 0; r < 16; r++) { vre[r] = sRe[b4 + r]; vim[r] = sIm[b4 + r]; }
            applyW(gRY[L * NQ + 12], 0);
            {
                float2 g = gRY[L * NQ + 13];
                ull ca = bc(g.x), nsps = pk2(-g.y, g.y);
                #pragma unroll
                for (int r = 0; r < 16; r++) {
                    vre[r] = f2fma(ca, vre[r], f2mul(nsps, swp(vre[r])));
                    vim[r] = f2fma(ca, vim[r], f2mul(nsps, swp(vim[r])));
                }
            }
            {
                float fr = PhiRe[L * 128 + (t >> 2)];
                float fi = PhiIm[L * 128 + (t >> 2)];
                ull fr2 = bc(fr), fi2 = bc(fi), nfi2 = bc(-fi), n1 = bc(-1.f);
                const int c = t & 3;
                #pragma unroll
                for (int r = 0; r < 16; r++) {
                    ull pr2 = PloRe[L * 64 + r * 4 + c];
                    ull pi2 = PloIm[L * 64 + r * 4 + c];
                    ull cr  = f2fma(fr2, pr2, f2mul(nfi2, pi2));
                    ull ci  = f2fma(fr2, pi2, f2mul(fi2, pr2));
                    ull nci = f2mul(n1, ci);
                    ull re = vre[r], im = vim[r];
                    vre[r] = f2fma(cr, re, f2mul(nci, im));
                    vim[r] = f2fma(cr, im, f2mul(ci,  re));
                }
            }
            #pragma unroll
            for (int r = 0; r < 16; r++) { sRe[b4 + r] = vre[r]; sIm[b4 + r] = vim[r]; }
        }
        __syncthreads();

        if (L < 2) {
            // ---- P1' of next layer with CNOT-chain fold ----
            const int e  = t ^ (t >> 1);
            const int eh = e >> 4;
            #pragma unroll
            for (int r = 0; r < 16; r++) {
                const int C = (r << 1) ^ r;          // compile-time
                int p = e ^ (C << 8);
                int a = p + (eh ^ (C << 4));
                vre[r] = sRe[a]; vim[r] = sIm[a];
            }
            if (t & 1) {
                #pragma unroll
                for (int r = 0; r < 16; r++) { vre[r] = swp(vre[r]); vim[r] = swp(vim[r]); }
            }
            #pragma unroll
            for (int lb = 0; lb < 4; lb++) applyW(gRY[(L + 1) * NQ + (3 - lb)], lb);
            __syncthreads();   // all reads done before any rewrite
            #pragma unroll
            for (int r = 0; r < 16; r++) { sRe[b1 + 544 * r] = vre[r]; sIm[b1 + 544 * r] = vim[r]; }
            __syncthreads();
        }
    }

    // ---- measurement: final chain folded into weight lookup ----
    {
        const int ftt = pf_(t << 5);
        ull acc2 = bc(0.f);
        #pragma unroll
        for (int k = 0; k < 16; k++) {
            ull re = sRe[b4 + k], im = sIm[b4 + k];
            ull pr2 = f2fma(im, im, f2mul(re, re));
            int f0 = ftt ^ pf_(k << 1);
            float w0 = WloF[f0 & 127]       + Whi[f0 >> 7];
            float w1 = WloF[(f0 ^ 1) & 127] + Whi[f0 >> 7];
            acc2 = f2fma(pr2, pk2(w0, w1), acc2);
        }
        float2 ac = upk(acc2);
        float acc = ac.x + ac.y;
        #pragma unroll
        for (int o = 16; o > 0; o >>= 1)
            acc += __shfl_xor_sync(0xffffffffu, acc, o);
        if ((t & 31) == 0) red[t >> 5] = acc;
        __syncthreads();
        if (t == 0) {
            float s = 0.f;
            #pragma unroll
            for (int w = 0; w < TPB / 32; w++) s += red[w];
            out[b] = s + hb[0];
        }
    }
}

extern "C" void kernel_launch(void* const* d_in, const int* in_sizes, int n_in,
                              void* d_out, int out_size) {
    const float* sb = (const float*)d_in[0];
    const float* vp = (const float*)d_in[1];
    const float* hw = (const float*)d_in[2];
    const float* hb = (const float*)d_in[3];
    float* out = (float*)d_out;

    const int B = in_sizes[0] / NQ;
    const size_t smem = (size_t)(SPAD * 2 + 192 * 2 + 64) * 8   // sRe,sIm,Plo*,Wlo2
                      + 96 * 8                                  // gRY, phw
                      + (384 * 2 + 32 + 128 + 16) * 4;          // PhiRe/Im,cx,sx,Whi,red
    cudaFuncSetAttribute(qsim_kernel,
                         cudaFuncAttributeMaxDynamicSharedMemorySize, (int)smem);
    qsim_kernel<<<B, TPB, smem>>>(sb, vp, hw, hb, out);
}

// round 6
// speedup vs baseline: 1.4719x; 1.0321x over previous
#include <cuda_runtime.h>
#include <cstdint>

#define NQ   14
#define TPB  512
typedef unsigned long long ull;

// forward CNOT-chain map: bit k of result = parity of bits k..13
__device__ __forceinline__ int pf_(int x) {
    x ^= x >> 1; x ^= x >> 2; x ^= x >> 4; x ^= x >> 8;
    return x;
}

// ---- packed f32x2 on native 64-bit regs ----
__device__ __forceinline__ ull f2mul(ull a, ull b) {
    ull r; asm("mul.rn.f32x2 %0,%1,%2;" : "=l"(r) : "l"(a), "l"(b)); return r;
}
__device__ __forceinline__ ull f2fma(ull a, ull b, ull c) {
    ull r; asm("fma.rn.f32x2 %0,%1,%2,%3;" : "=l"(r) : "l"(a), "l"(b), "l"(c)); return r;
}
__device__ __forceinline__ ull pk2(float x, float y) {
    ull r; asm("mov.b64 %0,{%1,%2};" : "=l"(r) : "f"(x), "f"(y)); return r;
}
__device__ __forceinline__ float2 upk(ull a) {
    float2 r; asm("mov.b64 {%0,%1},%2;" : "=f"(r.x), "=f"(r.y) : "l"(a)); return r;
}
__device__ __forceinline__ ull swp(ull a) { float2 t = upk(a); return pk2(t.y, t.x); }
__device__ __forceinline__ ull bc(float x) { return pk2(x, x); }

__device__ __forceinline__ void ryp(ull& u0, ull& u1, ull ca, ull sa, ull nsa) {
    ull t0 = f2fma(nsa, u1, f2mul(ca, u0));
    ull t1 = f2fma(ca,  u1, f2mul(sa, u0));
    u0 = t0; u1 = t1;
}

__device__ __forceinline__ float2 cmul_s(float2 a, float2 b) {
    return make_float2(a.x * b.x - a.y * b.y, a.x * b.y + a.y * b.x);
}

#define SPAD 8704   // 8192 pairs + 512 pad (1 per 16), pad A(p)=p+(p>>4)

__global__ void __launch_bounds__(TPB, 1)
qsim_kernel(const float* __restrict__ sb, const float* __restrict__ vp,
            const float* __restrict__ hw, const float* __restrict__ hb,
            float* __restrict__ out)
{
    extern __shared__ unsigned char smraw[];
    ull*    sRe   = (ull*)smraw;             // 8704
    ull*    sIm   = sRe + SPAD;              // 8704
    ull*    PloRe = sIm + SPAD;              // 2*64 (layers 0,1 only)
    ull*    PloIm = PloRe + 128;             // 2*64
    ull*    Wlo2  = PloIm + 128;             // 64 (scalar view Wlo[128])
    float2* gRY   = (float2*)(Wlo2 + 64);    // 48 (42 used)
    float2* phw   = gRY + 48;                // 48 (28 used)
    float*  PhiRe = (float*)(phw + 48);      // 256
    float*  PhiIm = PhiRe + 256;             // 256
    float*  cx    = PhiIm + 256;             // 16
    float*  sx    = cx + 16;                 // 16
    float*  Whi   = sx + 16;                 // 128
    float*  red   = Whi + 128;               // 16
    float*  WloF  = (float*)Wlo2;

    const int t = threadIdx.x;
    const int b = blockIdx.x;

    // ---- stage 1 ----
    if (t < NQ) {
        float s, c; sincosf(0.5f * sb[b * NQ + t], &s, &c);
        cx[t] = c; sx[t] = s;
    }
    if (t >= 64 && t < 64 + 3 * NQ) {
        int lw = t - 64;
        float sa, ca;
        sincosf(0.5f * vp[lw * 3 + 0], &sa, &ca);
        gRY[lw] = make_float2(ca, sa);
        if (lw < 2 * NQ) {                       // RZ phases only needed for L=0,1
            float sp, cp;
            sincosf(vp[lw * 3 + 1], &sp, &cp);
            phw[lw] = make_float2(cp, sp);
        }
    }
    if (t >= 160 && t < 288) {
        int v = t - 160; float acc = 0.f;
        #pragma unroll
        for (int k = 0; k < 7; k++)
            acc += hw[13 - k] * (1.f - 2.f * (float)((v >> k) & 1));
        WloF[v] = acc;
    }
    if (t >= 288 && t < 416) {
        int v = t - 288; float acc = 0.f;
        #pragma unroll
        for (int k = 0; k < 7; k++)
            acc += hw[6 - k] * (1.f - 2.f * (float)((v >> k) & 1));
        Whi[v] = acc;
    }
    __syncthreads();

    // ---- stage 2: consolidated RZ phase LUTs for layers 0,1 ----
    if (t < 256) {
        int L = t >> 7, v = t & 127;
        float2 pl = make_float2(1.f, 0.f), ph = make_float2(1.f, 0.f);
        #pragma unroll
        for (int k = 0; k < 7; k++) {
            if ((v >> k) & 1) {
                pl = cmul_s(pl, phw[L * NQ + (13 - k)]);
                ph = cmul_s(ph, phw[L * NQ + (6 - k)]);
            }
        }
        PhiRe[t] = ph.x; PhiIm[t] = ph.y;
        int c = v >> 5, r = (v >> 1) & 15, b0 = v & 1;
        ((float*)PloRe)[2 * (L * 64 + r * 4 + c) + b0] = pl.x;
        ((float*)PloIm)[2 * (L * 64 + r * 4 + c) + b0] = pl.y;
    }

    ull vre[16], vim[16];

    auto applyW = [&](float2 g, int lb) {
        ull ca = bc(g.x), sa = bc(g.y), nsa = bc(-g.y);
        #pragma unroll
        for (int m = 0; m < 8; m++) {
            int l0 = ((m >> lb) << (lb + 1)) | (m & ((1 << lb) - 1));
            int l1 = l0 | (1 << lb);
            ryp(vre[l0], vre[l1], ca, sa, nsa);
            ryp(vim[l0], vim[l1], ca, sa, nsa);
        }
    };

    // affine pass bases (padding A(p) = p + (p>>4))
    const int b1 = t + (t >> 4);                               // + 544*r
    const int b2 = (t >> 5) * 544 + (t & 31) + ((t >> 4) & 1); // + 34*r
    const int b3 = 34 * (t >> 1) + (t & 1);                    // + 2r + (r>>3)
    const int b4 = 17 * t;                                     // + r

    // ---- init: closed-form RX + layer-0 wires 0..3 ----
    {
        float mt = 1.f;
        #pragma unroll
        for (int k = 0; k < 9; k++)
            mt *= ((t >> k) & 1) ? sx[12 - k] : cx[12 - k];
        int pt = __popc(t);
        #pragma unroll
        for (int r = 0; r < 16; r++) {
            float mr = mt;
            #pragma unroll
            for (int m = 0; m < 4; m++)
                mr *= ((r >> m) & 1) ? sx[3 - m] : cx[3 - m];
            int pr = pt + __popc(r);
            float m0 = mr * cx[13], m1 = mr * sx[13];
            int k0 = pr & 3, k1 = (pr + 1) & 3;
            float re0 = (k0 == 0) ? m0 : ((k0 == 2) ? -m0 : 0.f);
            float im0 = (k0 == 1) ? -m0 : ((k0 == 3) ? m0 : 0.f);
            float re1 = (k1 == 0) ? m1 : ((k1 == 2) ? -m1 : 0.f);
            float im1 = (k1 == 1) ? -m1 : ((k1 == 3) ? m1 : 0.f);
            vre[r] = pk2(re0, re1); vim[r] = pk2(im0, im1);
        }
        #pragma unroll
        for (int lb = 0; lb < 4; lb++) applyW(gRY[3 - lb], lb);
        #pragma unroll
        for (int r = 0; r < 16; r++) { sRe[b1 + 544 * r] = vre[r]; sIm[b1 + 544 * r] = vim[r]; }
    }
    __syncthreads();

    #pragma unroll 1
    for (int L = 0; L < 3; L++) {
        // ---- P2: wires 4..7 ----
        {
            #pragma unroll
            for (int r = 0; r < 16; r++) { vre[r] = sRe[b2 + 34 * r]; vim[r] = sIm[b2 + 34 * r]; }
            #pragma unroll
            for (int lb = 0; lb < 4; lb++) applyW(gRY[L * NQ + (7 - lb)], lb);
            #pragma unroll
            for (int r = 0; r < 16; r++) { sRe[b2 + 34 * r] = vre[r]; sIm[b2 + 34 * r] = vim[r]; }
        }
        __syncthreads();

        // ---- P3: wires 8..11 ----
        {
            #pragma unroll
            for (int r = 0; r < 16; r++) {
                int o = b3 + 2 * r + (r >> 3);
                vre[r] = sRe[o]; vim[r] = sIm[o];
            }
            #pragma unroll
            for (int lb = 0; lb < 4; lb++) applyW(gRY[L * NQ + (11 - lb)], lb);
            #pragma unroll
            for (int r = 0; r < 16; r++) {
                int o = b3 + 2 * r + (r >> 3);
                sRe[o] = vre[r]; sIm[o] = vim[r];
            }
        }
        __syncthreads();

        // ---- P4: wires 12,13; phase for L<2; fused measurement at L=2 ----
        {
            #pragma unroll
            for (int r = 0; r < 16; r++) { vre[r] = sRe[b4 + r]; vim[r] = sIm[b4 + r]; }
            applyW(gRY[L * NQ + 12], 0);
            {
                float2 g = gRY[L * NQ + 13];
                ull ca = bc(g.x), nsps = pk2(-g.y, g.y);
                #pragma unroll
                for (int r = 0; r < 16; r++) {
                    vre[r] = f2fma(ca, vre[r], f2mul(nsps, swp(vre[r])));
                    vim[r] = f2fma(ca, vim[r], f2mul(nsps, swp(vim[r])));
                }
            }
            if (L < 2) {
                // consolidated layer phase (|psi|^2-relevant only for L<2)
                float fr = PhiRe[L * 128 + (t >> 2)];
                float fi = PhiIm[L * 128 + (t >> 2)];
                ull fr2 = bc(fr), fi2 = bc(fi), nfi2 = bc(-fi), n1 = bc(-1.f);
                const int c = t & 3;
                #pragma unroll
                for (int r = 0; r < 16; r++) {
                    ull pr2 = PloRe[L * 64 + r * 4 + c];
                    ull pi2 = PloIm[L * 64 + r * 4 + c];
                    ull cr  = f2fma(fr2, pr2, f2mul(nfi2, pi2));
                    ull ci  = f2fma(fr2, pi2, f2mul(fi2, pr2));
                    ull nci = f2mul(n1, ci);
                    ull re = vre[r], im = vim[r];
                    vre[r] = f2fma(cr, re, f2mul(nci, im));
                    vim[r] = f2fma(cr, im, f2mul(ci,  re));
                }
                #pragma unroll
                for (int r = 0; r < 16; r++) { sRe[b4 + r] = vre[r]; sIm[b4 + r] = vim[r]; }
            } else {
                // ---- measurement straight from registers (chain folded) ----
                const int ftt = pf_(t << 5);
                const float whi = Whi[ftt >> 7];
                ull acc2 = bc(0.f);
                #pragma unroll
                for (int k = 0; k < 16; k++) {
                    ull pr2 = f2fma(vim[k], vim[k], f2mul(vre[k], vre[k]));
                    int f0 = (ftt ^ pf_(k << 1)) & 127;   // pf_(k<<1) compile-time
                    float w0 = WloF[f0]     + whi;
                    float w1 = WloF[f0 ^ 1] + whi;
                    acc2 = f2fma(pr2, pk2(w0, w1), acc2);
                }
                float2 ac = upk(acc2);
                float acc = ac.x + ac.y;
                #pragma unroll
                for (int o = 16; o > 0; o >>= 1)
                    acc += __shfl_xor_sync(0xffffffffu, acc, o);
                if ((t & 31) == 0) red[t >> 5] = acc;
                __syncthreads();
                if (t == 0) {
                    float s = 0.f;
                    #pragma unroll
                    for (int w = 0; w < TPB / 32; w++) s += red[w];
                    out[b] = s + hb[0];
                }
            }
        }

        if (L < 2) {
            __syncthreads();
            // ---- P1' of next layer with CNOT-chain fold ----
            const int e  = t ^ (t >> 1);
            const int eh = e >> 4;
            #pragma unroll
            for (int r = 0; r < 16; r++) {
                const int C = (r << 1) ^ r;          // compile-time
                int p = e ^ (C << 8);
                int a = p + (eh ^ (C << 4));
                vre[r] = sRe[a]; vim[r] = sIm[a];
            }
            if (t & 1) {
                #pragma unroll
                for (int r = 0; r < 16; r++) { vre[r] = swp(vre[r]); vim[r] = swp(vim[r]); }
            }
            #pragma unroll
            for (int lb = 0; lb < 4; lb++) applyW(gRY[(L + 1) * NQ + (3 - lb)], lb);
            __syncthreads();   // all reads done before any rewrite
            #pragma unroll
            for (int r = 0; r < 16; r++) { sRe[b1 + 544 * r] = vre[r]; sIm[b1 + 544 * r] = vim[r]; }
            __syncthreads();
        }
    }
}

extern "C" void kernel_launch(void* const* d_in, const int* in_sizes, int n_in,
                              void* d_out, int out_size) {
    const float* sb = (const float*)d_in[0];
    const float* vp = (const float*)d_in[1];
    const float* hw = (const float*)d_in[2];
    const float* hb = (const float*)d_in[3];
    float* out = (float*)d_out;

    const int B = in_sizes[0] / NQ;
    const size_t smem = (size_t)(SPAD * 2 + 128 * 2 + 64) * 8   // sRe,sIm,Plo*,Wlo2
                      + 96 * 8                                  // gRY, phw
                      + (256 * 2 + 32 + 128 + 16) * 4;          // PhiRe/Im,cx,sx,Whi,red
    cudaFuncSetAttribute(qsim_kernel,
                         cudaFuncAttributeMaxDynamicSharedMemorySize, (int)smem);
    qsim_kernel<<<B, TPB, smem>>>(sb, vp, hw, hb, out);
}